// round 1
// baseline (speedup 1.0000x reference)
#include <cuda_runtime.h>
#include <cuda_bf16.h>
#include <math_constants.h>

// Problem dims (fixed per reference)
#define DM   1024      // d_model
#define DF   4096      // d_ff
#define MROWS 16384    // 4 * 4096

// Scratch (allocation-free: __device__ globals)
__device__ float g_scores[(size_t)MROWS * DF];   // 256 MB
__device__ float g_xscale[MROWS];
__device__ float g_wscale[DF];

// ---------------------------------------------------------------------------
// Kernel 0: per-row rms scale  s[r] = rsqrt(mean(v^2) + eps)
// one block (256 thr) per row of length 1024
// ---------------------------------------------------------------------------
__global__ void rms_scale_kernel(const float* __restrict__ X, float* __restrict__ out)
{
    const int row = blockIdx.x;
    const int tid = threadIdx.x;
    const float* p = X + (size_t)row * DM;

    float s = 0.f;
    // 1024 / 256 = 4 elements per thread, use float4
    float4 v = *(const float4*)(p + tid * 4);
    s = v.x * v.x + v.y * v.y + v.z * v.z + v.w * v.w;

    __shared__ float red[256];
    red[tid] = s;
    __syncthreads();
    #pragma unroll
    for (int off = 128; off > 0; off >>= 1) {
        if (tid < off) red[tid] += red[tid + off];
        __syncthreads();
    }
    if (tid == 0)
        out[row] = rsqrtf(red[0] * (1.0f / DM) + 1e-6f);
}

// ---------------------------------------------------------------------------
// Kernel 1: NT SGEMM  scores[m,n] = (A[m,:] . B[n,:]) * xs[m] * ws[n]
// A: [MROWS, 1024]  B: [4096, 1024]  C: [MROWS, 4096]
// BM=BN=128, BK=16, 256 threads, 8x8 per thread
// ---------------------------------------------------------------------------
#define BM 128
#define BN 128
#define BK 16

__global__ __launch_bounds__(256) void gemm_nt_scores(
    const float* __restrict__ A, const float* __restrict__ B)
{
    __shared__ float As[BK][BM];
    __shared__ float Bs[BK][BN];

    const int bn = blockIdx.x;   // over DF/BN = 32
    const int bm = blockIdx.y;   // over MROWS/BM = 128
    const int tid = threadIdx.x;

    const float* Ab = A + (size_t)bm * BM * DM;
    const float* Bb = B + (size_t)bn * BN * DM;

    float acc[8][8];
    #pragma unroll
    for (int i = 0; i < 8; i++)
        #pragma unroll
        for (int j = 0; j < 8; j++) acc[i][j] = 0.f;

    const int rL = tid >> 2;          // 0..63  (tile row for loads)
    const int cL = (tid & 3) * 4;     // 0,4,8,12 (k-col, float4)
    const int tr = (tid >> 4) * 8;    // 0..120 (compute row base)
    const int tc = (tid & 15) * 8;    // 0..120 (compute col base)

    for (int k0 = 0; k0 < DM; k0 += BK) {
        #pragma unroll
        for (int i = 0; i < 2; i++) {
            const int r = rL + i * 64;
            float4 va = *(const float4*)(Ab + (size_t)r * DM + k0 + cL);
            As[cL + 0][r] = va.x; As[cL + 1][r] = va.y;
            As[cL + 2][r] = va.z; As[cL + 3][r] = va.w;
            float4 vb = *(const float4*)(Bb + (size_t)r * DM + k0 + cL);
            Bs[cL + 0][r] = vb.x; Bs[cL + 1][r] = vb.y;
            Bs[cL + 2][r] = vb.z; Bs[cL + 3][r] = vb.w;
        }
        __syncthreads();

        #pragma unroll
        for (int kk = 0; kk < BK; kk++) {
            float4 a0 = *(const float4*)&As[kk][tr];
            float4 a1 = *(const float4*)&As[kk][tr + 4];
            float4 b0 = *(const float4*)&Bs[kk][tc];
            float4 b1 = *(const float4*)&Bs[kk][tc + 4];
            float ra[8] = {a0.x, a0.y, a0.z, a0.w, a1.x, a1.y, a1.z, a1.w};
            float rb[8] = {b0.x, b0.y, b0.z, b0.w, b1.x, b1.y, b1.z, b1.w};
            #pragma unroll
            for (int i = 0; i < 8; i++)
                #pragma unroll
                for (int j = 0; j < 8; j++)
                    acc[i][j] += ra[i] * rb[j];
        }
        __syncthreads();
    }

    const int gm = bm * BM + tr;
    const int gn = bn * BN + tc;
    #pragma unroll
    for (int i = 0; i < 8; i++) {
        const float xs = g_xscale[gm + i];
        float* crow = g_scores + (size_t)(gm + i) * DF + gn;
        #pragma unroll
        for (int j = 0; j < 8; j++)
            crow[j] = acc[i][j] * xs * g_wscale[gn + j];
    }
}

// ---------------------------------------------------------------------------
// Kernel 2: row softmax over 4096, in place. block=256 threads, 16 elems/thr
// ---------------------------------------------------------------------------
__global__ __launch_bounds__(256) void softmax_rows(float* __restrict__ S)
{
    const int row = blockIdx.x;
    const int tid = threadIdx.x;
    float* p = S + (size_t)row * DF;

    float v[16];
    float lm = -CUDART_INF_F;
    #pragma unroll
    for (int j = 0; j < 16; j++) {
        v[j] = p[tid + j * 256];
        lm = fmaxf(lm, v[j]);
    }

    __shared__ float red[256];
    red[tid] = lm;
    __syncthreads();
    #pragma unroll
    for (int off = 128; off > 0; off >>= 1) {
        if (tid < off) red[tid] = fmaxf(red[tid], red[tid + off]);
        __syncthreads();
    }
    const float m = red[0];
    __syncthreads();

    float ls = 0.f;
    #pragma unroll
    for (int j = 0; j < 16; j++) {
        v[j] = __expf(v[j] - m);
        ls += v[j];
    }
    red[tid] = ls;
    __syncthreads();
    #pragma unroll
    for (int off = 128; off > 0; off >>= 1) {
        if (tid < off) red[tid] += red[tid + off];
        __syncthreads();
    }
    const float inv = 1.0f / red[0];
    #pragma unroll
    for (int j = 0; j < 16; j++)
        p[tid + j * 256] = v[j] * inv;
}

// ---------------------------------------------------------------------------
// Kernel 3: NN SGEMM  out[m,d] = sum_c probs[m,c] * W[c,d]
// A = g_scores [MROWS, 4096], B = W [4096, 1024], C = out [MROWS, 1024]
// ---------------------------------------------------------------------------
__global__ __launch_bounds__(256) void gemm_nn_out(
    const float* __restrict__ B, float* __restrict__ C)
{
    __shared__ float As[BK][BM];
    __shared__ float Bs[BK][BN];

    const int bn = blockIdx.x;   // over DM/BN = 8
    const int bm = blockIdx.y;   // over MROWS/BM = 128
    const int tid = threadIdx.x;

    const float* Ab = g_scores + (size_t)bm * BM * DF;
    const float* Bb = B + (size_t)bn * BN;

    float acc[8][8];
    #pragma unroll
    for (int i = 0; i < 8; i++)
        #pragma unroll
        for (int j = 0; j < 8; j++) acc[i][j] = 0.f;

    const int rA = tid >> 2;          // 0..63
    const int cA = (tid & 3) * 4;     // k-col float4
    const int rB = tid >> 5;          // 0..7  (k-row for B loads)
    const int cB = (tid & 31) * 4;    // 0..124 (n-col float4)
    const int tr = (tid >> 4) * 8;
    const int tc = (tid & 15) * 8;

    for (int k0 = 0; k0 < DF; k0 += BK) {
        #pragma unroll
        for (int i = 0; i < 2; i++) {
            const int r = rA + i * 64;
            float4 va = *(const float4*)(Ab + (size_t)r * DF + k0 + cA);
            As[cA + 0][r] = va.x; As[cA + 1][r] = va.y;
            As[cA + 2][r] = va.z; As[cA + 3][r] = va.w;
        }
        #pragma unroll
        for (int i = 0; i < 2; i++) {
            const int r = rB + i * 8;
            float4 vb = *(const float4*)(Bb + (size_t)(k0 + r) * DM + cB);
            *(float4*)&Bs[r][cB] = vb;
        }
        __syncthreads();

        #pragma unroll
        for (int kk = 0; kk < BK; kk++) {
            float4 a0 = *(const float4*)&As[kk][tr];
            float4 a1 = *(const float4*)&As[kk][tr + 4];
            float4 b0 = *(const float4*)&Bs[kk][tc];
            float4 b1 = *(const float4*)&Bs[kk][tc + 4];
            float ra[8] = {a0.x, a0.y, a0.z, a0.w, a1.x, a1.y, a1.z, a1.w};
            float rb[8] = {b0.x, b0.y, b0.z, b0.w, b1.x, b1.y, b1.z, b1.w};
            #pragma unroll
            for (int i = 0; i < 8; i++)
                #pragma unroll
                for (int j = 0; j < 8; j++)
                    acc[i][j] += ra[i] * rb[j];
        }
        __syncthreads();
    }

    const int gm = bm * BM + tr;
    const int gn = bn * BN + tc;
    #pragma unroll
    for (int i = 0; i < 8; i++) {
        float* crow = C + (size_t)(gm + i) * DM + gn;
        #pragma unroll
        for (int j = 0; j < 4; j++) {
            // vector store pairs of 4
        }
        *(float4*)(crow)     = make_float4(acc[i][0], acc[i][1], acc[i][2], acc[i][3]);
        *(float4*)(crow + 4) = make_float4(acc[i][4], acc[i][5], acc[i][6], acc[i][7]);
    }
}

// ---------------------------------------------------------------------------
// Launch
// ---------------------------------------------------------------------------
extern "C" void kernel_launch(void* const* d_in, const int* in_sizes, int n_in,
                              void* d_out, int out_size)
{
    const float* x = (const float*)d_in[0];   // [4,4096,1024] -> [16384,1024]
    const float* w = (const float*)d_in[1];   // [4096,1024]
    float* out = (float*)d_out;               // [16384,1024]

    float* xscale; float* wscale; float* scores;
    cudaGetSymbolAddress((void**)&xscale, g_xscale);
    cudaGetSymbolAddress((void**)&wscale, g_wscale);
    cudaGetSymbolAddress((void**)&scores, g_scores);

    rms_scale_kernel<<<MROWS, 256>>>(x, xscale);
    rms_scale_kernel<<<DF,    256>>>(w, wscale);

    dim3 g1(DF / BN, MROWS / BM);      // 32 x 128
    gemm_nt_scores<<<g1, 256>>>(x, w);

    softmax_rows<<<MROWS, 256>>>(scores);

    dim3 g3(DM / BN, MROWS / BM);      // 8 x 128
    gemm_nn_out<<<g3, 256>>>(w, out);
}

// round 4
// speedup vs baseline: 1.4925x; 1.4925x over previous
#include <cuda_runtime.h>
#include <cuda_fp16.h>
#include <cstdint>
#include <math_constants.h>

// Problem dims (fixed per reference)
#define DM   1024      // d_model
#define DF   4096      // d_ff
#define MROWS 16384    // 4 * 4096

// ---------------------------------------------------------------------------
// Scratch (allocation-free: __device__ globals)
// ---------------------------------------------------------------------------
__device__ float  g_scores[(size_t)MROWS * DF];   // 256 MB fp32 logits
__device__ __half g_phi[(size_t)MROWS * DF];      // probs hi
__device__ __half g_plo[(size_t)MROWS * DF];      // probs lo
__device__ __half g_xhi[(size_t)MROWS * DM];      // (xs*x) hi
__device__ __half g_xlo[(size_t)MROWS * DM];
__device__ __half g_whi[(size_t)DF * DM];         // (ws*w) hi
__device__ __half g_wlo[(size_t)DF * DM];
__device__ __half g_wthi[(size_t)DM * DF];        // W^T (raw w) [d][c]
__device__ __half g_wtlo[(size_t)DM * DF];
__device__ float  g_xscale[MROWS];
__device__ float  g_wscale[DF];

// ---------------------------------------------------------------------------
// PTX helpers
// ---------------------------------------------------------------------------
__device__ __forceinline__ uint32_t smem_u32_of(const void* p) {
    uint32_t a;
    asm("{ .reg .u64 t; cvta.to.shared.u64 t, %1; cvt.u32.u64 %0, t; }" : "=r"(a) : "l"(p));
    return a;
}

__device__ __forceinline__ void cp16(uint32_t s, const void* g) {
    asm volatile("cp.async.cg.shared.global [%0], [%1], 16;" :: "r"(s), "l"(g));
}

__device__ __forceinline__ void ldsm4(uint32_t* r, uint32_t a) {
    asm volatile("ldmatrix.sync.aligned.m8n8.x4.shared.b16 {%0,%1,%2,%3}, [%4];"
                 : "=r"(r[0]), "=r"(r[1]), "=r"(r[2]), "=r"(r[3]) : "r"(a));
}

__device__ __forceinline__ void mma16816(float* d, const uint32_t* a, const uint32_t* b) {
    asm volatile(
        "mma.sync.aligned.m16n8k16.row.col.f32.f16.f16.f32 "
        "{%0,%1,%2,%3}, {%4,%5,%6,%7}, {%8,%9}, {%0,%1,%2,%3};"
        : "+f"(d[0]), "+f"(d[1]), "+f"(d[2]), "+f"(d[3])
        : "r"(a[0]), "r"(a[1]), "r"(a[2]), "r"(a[3]), "r"(b[0]), "r"(b[1]));
}

// ---------------------------------------------------------------------------
// Kernel: per-row rms scale  s[r] = rsqrt(mean(v^2) + eps)
// ---------------------------------------------------------------------------
__global__ void rms_scale_kernel(const float* __restrict__ X, float* __restrict__ out)
{
    const int row = blockIdx.x;
    const int tid = threadIdx.x;
    const float* p = X + (size_t)row * DM;

    float4 v = *(const float4*)(p + tid * 4);
    float s = v.x * v.x + v.y * v.y + v.z * v.z + v.w * v.w;

    __shared__ float red[256];
    red[tid] = s;
    __syncthreads();
    #pragma unroll
    for (int off = 128; off > 0; off >>= 1) {
        if (tid < off) red[tid] += red[tid + off];
        __syncthreads();
    }
    if (tid == 0)
        out[row] = rsqrtf(red[0] * (1.0f / DM) + 1e-6f);
}

// ---------------------------------------------------------------------------
// Kernel: fused scale + fp16 hi/lo split  (row length = DM = 1024)
// ---------------------------------------------------------------------------
__device__ __forceinline__ void split2h(float v, __half& h, __half& l) {
    h = __float2half_rn(v);
    l = __float2half_rn(v - __half2float(h));
}

__global__ __launch_bounds__(256) void scale_split_kernel(
    const float* __restrict__ src, const float* __restrict__ scale,
    __half* __restrict__ hi, __half* __restrict__ lo)
{
    const size_t i = (size_t)blockIdx.x * 256 + threadIdx.x;  // one float4 per thread
    float4 v = ((const float4*)src)[i];
    const float s = scale[i >> 8];   // element row = (4i)>>10 = i>>8
    __half h0, h1, h2, h3, l0, l1, l2, l3;
    split2h(v.x * s, h0, l0); split2h(v.y * s, h1, l1);
    split2h(v.z * s, h2, l2); split2h(v.w * s, h3, l3);
    __half2* H = (__half2*)(hi + 4 * i);
    __half2* L = (__half2*)(lo + 4 * i);
    H[0] = __halves2half2(h0, h1); H[1] = __halves2half2(h2, h3);
    L[0] = __halves2half2(l0, l1); L[1] = __halves2half2(l2, l3);
}

// ---------------------------------------------------------------------------
// Kernel: transpose + split  W[c,d] -> Wt_hi/lo[d,c]   (raw W, no scale)
// ---------------------------------------------------------------------------
__global__ void wt_split_kernel(const float* __restrict__ w,
                                __half* __restrict__ th, __half* __restrict__ tl)
{
    __shared__ float t[32][33];
    const int c = blockIdx.y * 32 + threadIdx.y;
    const int d = blockIdx.x * 32 + threadIdx.x;
    t[threadIdx.y][threadIdx.x] = w[(size_t)c * DM + d];
    __syncthreads();
    const int dd = blockIdx.x * 32 + threadIdx.y;
    const int cc = blockIdx.y * 32 + threadIdx.x;
    float v = t[threadIdx.x][threadIdx.y];
    __half h, l;
    split2h(v, h, l);
    th[(size_t)dd * DF + cc] = h;
    tl[(size_t)dd * DF + cc] = l;
}

// ---------------------------------------------------------------------------
// Kernel: row softmax over 4096, emits fp16 hi/lo probs
// ---------------------------------------------------------------------------
__global__ __launch_bounds__(256) void softmax_split(const float* __restrict__ S,
                                                     __half* __restrict__ PH,
                                                     __half* __restrict__ PL)
{
    const int row = blockIdx.x;
    const int tid = threadIdx.x;
    const float* p = S + (size_t)row * DF + tid * 16;

    float v[16];
    #pragma unroll
    for (int j = 0; j < 4; j++) {
        float4 t = *(const float4*)(p + j * 4);
        v[j * 4 + 0] = t.x; v[j * 4 + 1] = t.y;
        v[j * 4 + 2] = t.z; v[j * 4 + 3] = t.w;
    }
    float lm = v[0];
    #pragma unroll
    for (int j = 1; j < 16; j++) lm = fmaxf(lm, v[j]);

    __shared__ float red[256];
    red[tid] = lm;
    __syncthreads();
    #pragma unroll
    for (int off = 128; off > 0; off >>= 1) {
        if (tid < off) red[tid] = fmaxf(red[tid], red[tid + off]);
        __syncthreads();
    }
    const float m = red[0];
    __syncthreads();

    float ls = 0.f;
    #pragma unroll
    for (int j = 0; j < 16; j++) {
        v[j] = __expf(v[j] - m);
        ls += v[j];
    }
    red[tid] = ls;
    __syncthreads();
    #pragma unroll
    for (int off = 128; off > 0; off >>= 1) {
        if (tid < off) red[tid] += red[tid + off];
        __syncthreads();
    }
    const float inv = 1.0f / red[0];

    __half2* ph2 = (__half2*)(PH + (size_t)row * DF + tid * 16);
    __half2* pl2 = (__half2*)(PL + (size_t)row * DF + tid * 16);
    #pragma unroll
    for (int j = 0; j < 8; j++) {
        float p0 = v[2 * j] * inv, p1 = v[2 * j + 1] * inv;
        __half h0, h1, l0, l1;
        split2h(p0, h0, l0); split2h(p1, h1, l1);
        ph2[j] = __halves2half2(h0, h1);
        pl2[j] = __halves2half2(l0, l1);
    }
}

// ---------------------------------------------------------------------------
// Split-fp16 NT GEMM via mma.sync.m16n8k16:
//   C[m,n] = sum_k (Ah+Al)[m,k] * (Bh+Bl)[n,k]   (al*bl dropped; ~fp32 exact)
// BM=BN=128, BK=32, 8 warps (2x4, 64x32 warp tile), 4-stage cp.async ring.
// smem tile: 128 rows x 40 halfs (80B rows, conflict-free ldmatrix).
// Tile offsets within a 40960B stage: Ah 0 | Al 10240 | Bh 20480 | Bl 30720.
// NT layout: both A and B tiles are [row][k] with k contiguous -> both use
// NON-trans ldmatrix (register pair must be k-consecutive for the fragments).
// ---------------------------------------------------------------------------
#define STAGEB 40960
#define GSMEM  (4 * STAGEB)   // 163840

__global__ __launch_bounds__(256, 1) void gemm_hsplit(
    const __half* __restrict__ Ah, const __half* __restrict__ Al,
    const __half* __restrict__ Bh, const __half* __restrict__ Bl,
    float* __restrict__ C, int lda, int ldb, int ldc, int KT)
{
    extern __shared__ __align__(16) char smem[];
    const uint32_t sbase = smem_u32_of(smem);
    const int tid  = threadIdx.x;
    const int lane = tid & 31;
    const int wid  = tid >> 5;
    const int wm   = (wid >> 2) * 64;   // warp m offset (0,64)
    const int wn   = (wid & 3) * 32;    // warp n offset (0..96)
    const int bm   = blockIdx.y * 128;
    const int bn   = blockIdx.x * 128;

    // loader mapping: thread t -> row lr = t>>2 (and lr+64), 16B chunk lc = t&3
    const int lr = tid >> 2;
    const int lc = tid & 3;
    const __half* pAh = Ah + (size_t)(bm + lr) * lda + lc * 8;
    const __half* pAl = Al + (size_t)(bm + lr) * lda + lc * 8;
    const __half* pBh = Bh + (size_t)(bn + lr) * ldb + lc * 8;
    const __half* pBl = Bl + (size_t)(bn + lr) * ldb + lc * 8;
    const size_t rstepA = (size_t)64 * lda;
    const size_t rstepB = (size_t)64 * ldb;
    const uint32_t so = lr * 80 + lc * 16;   // within-tile smem byte offset

    float acc[4][4][4];
    #pragma unroll
    for (int i = 0; i < 4; i++)
        #pragma unroll
        for (int j = 0; j < 4; j++)
            #pragma unroll
            for (int k = 0; k < 4; k++) acc[i][j][k] = 0.f;

#define LOAD_STAGE(kt)                                                        \
    do {                                                                      \
        const int _k0 = (kt) * 32;                                            \
        const uint32_t _sb = sbase + ((kt) & 3) * STAGEB + so;                \
        cp16(_sb + 0,     pAh + _k0);                                         \
        cp16(_sb + 5120,  pAh + _k0 + rstepA);                                \
        cp16(_sb + 10240, pAl + _k0);                                         \
        cp16(_sb + 15360, pAl + _k0 + rstepA);                                \
        cp16(_sb + 20480, pBh + _k0);                                         \
        cp16(_sb + 25600, pBh + _k0 + rstepB);                                \
        cp16(_sb + 30720, pBl + _k0);                                         \
        cp16(_sb + 35840, pBl + _k0 + rstepB);                                \
    } while (0)

    LOAD_STAGE(0); asm volatile("cp.async.commit_group;" ::: "memory");
    LOAD_STAGE(1); asm volatile("cp.async.commit_group;" ::: "memory");
    LOAD_STAGE(2); asm volatile("cp.async.commit_group;" ::: "memory");

    // ldmatrix base offsets (bytes)
    // A (non-trans): lanes 0-15 -> rows m0-15 @k0, lanes 16-31 -> rows m0-15 @k+8
    const uint32_t aoff = ((wm + (lane & 15)) * 40 + ((lane >> 4) << 3)) * 2;
    // B (non-trans): lanes 0-7 -> n0-7 @k0, 8-15 -> n0-7 @k+8,
    //                lanes 16-23 -> n8-15 @k0, 24-31 -> n8-15 @k+8
    const uint32_t boff = ((wn + (lane & 7) + ((lane >> 4) << 3)) * 40 + (lane & 8)) * 2;

    for (int kt = 0; kt < KT; ++kt) {
        asm volatile("cp.async.wait_group 2;" ::: "memory");
        __syncthreads();
        const uint32_t sb = sbase + (kt & 3) * STAGEB;

        #pragma unroll
        for (int ks = 0; ks < 2; ++ks) {
            const uint32_t kc2 = ks * 32;   // 16 halfs = 32 bytes
            uint32_t ahf[4][4], alf[4][4], bhf[4][2], blf[4][2];
            #pragma unroll
            for (int mt = 0; mt < 4; mt++) {
                ldsm4(ahf[mt], sb + aoff + kc2 + mt * 1280);
                ldsm4(alf[mt], sb + 10240 + aoff + kc2 + mt * 1280);
            }
            #pragma unroll
            for (int n2 = 0; n2 < 2; n2++) {
                uint32_t r[4];
                ldsm4(r, sb + 20480 + boff + kc2 + n2 * 1280);
                bhf[n2 * 2][0] = r[0]; bhf[n2 * 2][1] = r[1];
                bhf[n2 * 2 + 1][0] = r[2]; bhf[n2 * 2 + 1][1] = r[3];
                ldsm4(r, sb + 30720 + boff + kc2 + n2 * 1280);
                blf[n2 * 2][0] = r[0]; blf[n2 * 2][1] = r[1];
                blf[n2 * 2 + 1][0] = r[2]; blf[n2 * 2 + 1][1] = r[3];
            }
            #pragma unroll
            for (int mt = 0; mt < 4; mt++)
                #pragma unroll
                for (int nt = 0; nt < 4; nt++) {
                    mma16816(acc[mt][nt], ahf[mt], bhf[nt]);   // hi*hi
                    mma16816(acc[mt][nt], ahf[mt], blf[nt]);   // hi*lo
                    mma16816(acc[mt][nt], alf[mt], bhf[nt]);   // lo*hi
                }
        }
        __syncthreads();
        if (kt + 3 < KT) LOAD_STAGE(kt + 3);
        asm volatile("cp.async.commit_group;" ::: "memory");
    }

    // Epilogue: fp32 stores, standard m16n8 fragment mapping
    #pragma unroll
    for (int mt = 0; mt < 4; mt++) {
        const int row = bm + wm + mt * 16 + (lane >> 2);
        float* r0 = C + (size_t)row * ldc + bn + wn + (lane & 3) * 2;
        float* r1 = r0 + (size_t)8 * ldc;
        #pragma unroll
        for (int nt = 0; nt < 4; nt++) {
            *(float2*)(r0 + nt * 8) = make_float2(acc[mt][nt][0], acc[mt][nt][1]);
            *(float2*)(r1 + nt * 8) = make_float2(acc[mt][nt][2], acc[mt][nt][3]);
        }
    }
#undef LOAD_STAGE
}

// ---------------------------------------------------------------------------
// Launch
// ---------------------------------------------------------------------------
extern "C" void kernel_launch(void* const* d_in, const int* in_sizes, int n_in,
                              void* d_out, int out_size)
{
    const float* x = (const float*)d_in[0];   // [16384, 1024]
    const float* w = (const float*)d_in[1];   // [4096, 1024]
    float* out = (float*)d_out;               // [16384, 1024]

    float *xscale, *wscale, *scores;
    __half *xhi, *xlo, *whi, *wlo, *wthi, *wtlo, *phi, *plo;
    cudaGetSymbolAddress((void**)&xscale, g_xscale);
    cudaGetSymbolAddress((void**)&wscale, g_wscale);
    cudaGetSymbolAddress((void**)&scores, g_scores);
    cudaGetSymbolAddress((void**)&xhi, g_xhi);
    cudaGetSymbolAddress((void**)&xlo, g_xlo);
    cudaGetSymbolAddress((void**)&whi, g_whi);
    cudaGetSymbolAddress((void**)&wlo, g_wlo);
    cudaGetSymbolAddress((void**)&wthi, g_wthi);
    cudaGetSymbolAddress((void**)&wtlo, g_wtlo);
    cudaGetSymbolAddress((void**)&phi, g_phi);
    cudaGetSymbolAddress((void**)&plo, g_plo);

    cudaFuncSetAttribute(gemm_hsplit, cudaFuncAttributeMaxDynamicSharedMemorySize,
                         GSMEM);

    // Prep: rms scales; scaled fp16 splits; W transpose split
    rms_scale_kernel<<<MROWS, 256>>>(x, xscale);
    rms_scale_kernel<<<DF,    256>>>(w, wscale);
    scale_split_kernel<<<(MROWS * (DM / 4)) / 256, 256>>>(x, xscale, xhi, xlo);
    scale_split_kernel<<<(DF * (DM / 4)) / 256, 256>>>(w, wscale, whi, wlo);
    {
        dim3 g(DM / 32, DF / 32), b(32, 32);
        wt_split_kernel<<<g, b>>>(w, wthi, wtlo);
    }

    // GEMM1: scores[m,n] = (xs*x)_m . (ws*w)_n
    {
        dim3 g(DF / 128, MROWS / 128);   // 32 x 128
        gemm_hsplit<<<g, 256, GSMEM>>>(xhi, xlo, whi, wlo, scores,
                                       DM, DM, DF, DM / 32);
    }

    // softmax rows -> fp16 hi/lo probs
    softmax_split<<<MROWS, 256>>>(scores, phi, plo);

    // GEMM2: out[m,d] = sum_c probs[m,c] * w[c,d]  (B = W^T, K-major over c)
    {
        dim3 g(DM / 128, MROWS / 128);   // 8 x 128
        gemm_hsplit<<<g, 256, GSMEM>>>(phi, plo, wthi, wtlo, out,
                                       DF, DF, DM, DF / 32);
    }
}

// round 5
// speedup vs baseline: 3.4714x; 2.3258x over previous
#include <cuda_runtime.h>
#include <cuda_fp16.h>
#include <cstdint>
#include <math_constants.h>

// Problem dims (fixed per reference)
#define DM   1024      // d_model
#define DF   4096      // d_ff
#define MROWS 16384    // 4 * 4096

// ---------------------------------------------------------------------------
// Scratch (allocation-free: __device__ globals)
// ---------------------------------------------------------------------------
__device__ float  g_scores[(size_t)MROWS * DF];   // 256 MB fp32 logits
__device__ __half g_phi[(size_t)MROWS * DF];      // probs (single fp16)
__device__ __half g_xhi[(size_t)MROWS * DM];      // (xs*x) hi
__device__ __half g_xlo[(size_t)MROWS * DM];
__device__ __half g_whi[(size_t)DF * DM];         // (ws*w) hi
__device__ __half g_wlo[(size_t)DF * DM];
__device__ __half g_wthi[(size_t)DM * DF];        // W^T (raw w) [d][c], single fp16
__device__ float  g_xscale[MROWS];
__device__ float  g_wscale[DF];

// ---------------------------------------------------------------------------
// PTX helpers
// ---------------------------------------------------------------------------
__device__ __forceinline__ uint32_t smem_u32_of(const void* p) {
    uint32_t a;
    asm("{ .reg .u64 t; cvta.to.shared.u64 t, %1; cvt.u32.u64 %0, t; }" : "=r"(a) : "l"(p));
    return a;
}

__device__ __forceinline__ void cp16(uint32_t s, const void* g) {
    asm volatile("cp.async.cg.shared.global [%0], [%1], 16;" :: "r"(s), "l"(g));
}

__device__ __forceinline__ void ldsm4(uint32_t* r, uint32_t a) {
    asm volatile("ldmatrix.sync.aligned.m8n8.x4.shared.b16 {%0,%1,%2,%3}, [%4];"
                 : "=r"(r[0]), "=r"(r[1]), "=r"(r[2]), "=r"(r[3]) : "r"(a));
}

__device__ __forceinline__ void mma16816(float* d, const uint32_t* a, const uint32_t* b) {
    asm volatile(
        "mma.sync.aligned.m16n8k16.row.col.f32.f16.f16.f32 "
        "{%0,%1,%2,%3}, {%4,%5,%6,%7}, {%8,%9}, {%0,%1,%2,%3};"
        : "+f"(d[0]), "+f"(d[1]), "+f"(d[2]), "+f"(d[3])
        : "r"(a[0]), "r"(a[1]), "r"(a[2]), "r"(a[3]), "r"(b[0]), "r"(b[1]));
}

// ---------------------------------------------------------------------------
// Kernel: per-row rms scale  s[r] = rsqrt(mean(v^2) + eps)
// ---------------------------------------------------------------------------
__global__ void rms_scale_kernel(const float* __restrict__ X, float* __restrict__ out)
{
    const int row = blockIdx.x;
    const int tid = threadIdx.x;
    const float* p = X + (size_t)row * DM;

    float4 v = *(const float4*)(p + tid * 4);
    float s = v.x * v.x + v.y * v.y + v.z * v.z + v.w * v.w;

    __shared__ float red[256];
    red[tid] = s;
    __syncthreads();
    #pragma unroll
    for (int off = 128; off > 0; off >>= 1) {
        if (tid < off) red[tid] += red[tid + off];
        __syncthreads();
    }
    if (tid == 0)
        out[row] = rsqrtf(red[0] * (1.0f / DM) + 1e-6f);
}

// ---------------------------------------------------------------------------
// Kernel: fused scale + fp16 hi/lo split  (row length = DM = 1024)
// ---------------------------------------------------------------------------
__device__ __forceinline__ void split2h(float v, __half& h, __half& l) {
    h = __float2half_rn(v);
    l = __float2half_rn(v - __half2float(h));
}

__global__ __launch_bounds__(256) void scale_split_kernel(
    const float* __restrict__ src, const float* __restrict__ scale,
    __half* __restrict__ hi, __half* __restrict__ lo)
{
    const size_t i = (size_t)blockIdx.x * 256 + threadIdx.x;  // one float4 per thread
    float4 v = ((const float4*)src)[i];
    const float s = scale[i >> 8];   // element row = (4i)>>10 = i>>8
    __half h0, h1, h2, h3, l0, l1, l2, l3;
    split2h(v.x * s, h0, l0); split2h(v.y * s, h1, l1);
    split2h(v.z * s, h2, l2); split2h(v.w * s, h3, l3);
    __half2* H = (__half2*)(hi + 4 * i);
    __half2* L = (__half2*)(lo + 4 * i);
    H[0] = __halves2half2(h0, h1); H[1] = __halves2half2(h2, h3);
    L[0] = __halves2half2(l0, l1); L[1] = __halves2half2(l2, l3);
}

// ---------------------------------------------------------------------------
// Kernel: transpose  W[c,d] -> Wt[d,c]  (raw w, single fp16)
// ---------------------------------------------------------------------------
__global__ void wt_kernel(const float* __restrict__ w, __half* __restrict__ th)
{
    __shared__ float t[32][33];
    const int c = blockIdx.y * 32 + threadIdx.y;
    const int d = blockIdx.x * 32 + threadIdx.x;
    t[threadIdx.y][threadIdx.x] = w[(size_t)c * DM + d];
    __syncthreads();
    const int dd = blockIdx.x * 32 + threadIdx.y;
    const int cc = blockIdx.y * 32 + threadIdx.x;
    th[(size_t)dd * DF + cc] = __float2half_rn(t[threadIdx.x][threadIdx.y]);
}

// ---------------------------------------------------------------------------
// Kernel: row softmax over 4096, emits single fp16 probs
// ---------------------------------------------------------------------------
__global__ __launch_bounds__(256) void softmax_h(const float* __restrict__ S,
                                                 __half* __restrict__ PH)
{
    const int row = blockIdx.x;
    const int tid = threadIdx.x;
    const float* p = S + (size_t)row * DF + tid * 16;

    float v[16];
    #pragma unroll
    for (int j = 0; j < 4; j++) {
        float4 t = *(const float4*)(p + j * 4);
        v[j * 4 + 0] = t.x; v[j * 4 + 1] = t.y;
        v[j * 4 + 2] = t.z; v[j * 4 + 3] = t.w;
    }
    float lm = v[0];
    #pragma unroll
    for (int j = 1; j < 16; j++) lm = fmaxf(lm, v[j]);

    __shared__ float red[256];
    red[tid] = lm;
    __syncthreads();
    #pragma unroll
    for (int off = 128; off > 0; off >>= 1) {
        if (tid < off) red[tid] = fmaxf(red[tid], red[tid + off]);
        __syncthreads();
    }
    const float m = red[0];
    __syncthreads();

    float ls = 0.f;
    #pragma unroll
    for (int j = 0; j < 16; j++) {
        v[j] = __expf(v[j] - m);
        ls += v[j];
    }
    red[tid] = ls;
    __syncthreads();
    #pragma unroll
    for (int off = 128; off > 0; off >>= 1) {
        if (tid < off) red[tid] += red[tid + off];
        __syncthreads();
    }
    const float inv = 1.0f / red[0];

    __half2* ph2 = (__half2*)(PH + (size_t)row * DF + tid * 16);
    #pragma unroll
    for (int j = 0; j < 8; j++) {
        ph2[j] = __halves2half2(__float2half_rn(v[2 * j] * inv),
                                __float2half_rn(v[2 * j + 1] * inv));
    }
}

// ---------------------------------------------------------------------------
// Split-fp16 NT GEMM via mma.sync.m16n8k16 (3-term, ~fp32 exact):
//   C[m,n] = sum_k (Ah+Al)[m,k] * (Bh+Bl)[n,k]   (al*bl dropped)
// BM=BN=128, BK=32, 8 warps (2x4, 64x32 warp tile), 4-stage cp.async ring.
// smem tile: 128 rows x 40 halfs (80B rows, conflict-free ldmatrix).
// Both A and B tiles [row][k] k-contiguous -> NON-trans ldmatrix for both.
// ---------------------------------------------------------------------------
#define STAGEB 40960
#define GSMEM  (4 * STAGEB)   // 163840

__global__ __launch_bounds__(256, 1) void gemm_hsplit(
    const __half* __restrict__ Ah, const __half* __restrict__ Al,
    const __half* __restrict__ Bh, const __half* __restrict__ Bl,
    float* __restrict__ C, int lda, int ldb, int ldc, int KT)
{
    extern __shared__ __align__(16) char smem[];
    const uint32_t sbase = smem_u32_of(smem);
    const int tid  = threadIdx.x;
    const int lane = tid & 31;
    const int wid  = tid >> 5;
    const int wm   = (wid >> 2) * 64;   // warp m offset (0,64)
    const int wn   = (wid & 3) * 32;    // warp n offset (0..96)
    const int bm   = blockIdx.y * 128;
    const int bn   = blockIdx.x * 128;

    const int lr = tid >> 2;
    const int lc = tid & 3;
    const __half* pAh = Ah + (size_t)(bm + lr) * lda + lc * 8;
    const __half* pAl = Al + (size_t)(bm + lr) * lda + lc * 8;
    const __half* pBh = Bh + (size_t)(bn + lr) * ldb + lc * 8;
    const __half* pBl = Bl + (size_t)(bn + lr) * ldb + lc * 8;
    const size_t rstepA = (size_t)64 * lda;
    const size_t rstepB = (size_t)64 * ldb;
    const uint32_t so = lr * 80 + lc * 16;

    float acc[4][4][4];
    #pragma unroll
    for (int i = 0; i < 4; i++)
        #pragma unroll
        for (int j = 0; j < 4; j++)
            #pragma unroll
            for (int k = 0; k < 4; k++) acc[i][j][k] = 0.f;

#define LOAD_STAGE(kt)                                                        \
    do {                                                                      \
        const int _k0 = (kt) * 32;                                            \
        const uint32_t _sb = sbase + ((kt) & 3) * STAGEB + so;                \
        cp16(_sb + 0,     pAh + _k0);                                         \
        cp16(_sb + 5120,  pAh + _k0 + rstepA);                                \
        cp16(_sb + 10240, pAl + _k0);                                         \
        cp16(_sb + 15360, pAl + _k0 + rstepA);                                \
        cp16(_sb + 20480, pBh + _k0);                                         \
        cp16(_sb + 25600, pBh + _k0 + rstepB);                                \
        cp16(_sb + 30720, pBl + _k0);                                         \
        cp16(_sb + 35840, pBl + _k0 + rstepB);                                \
    } while (0)

    LOAD_STAGE(0); asm volatile("cp.async.commit_group;" ::: "memory");
    LOAD_STAGE(1); asm volatile("cp.async.commit_group;" ::: "memory");
    LOAD_STAGE(2); asm volatile("cp.async.commit_group;" ::: "memory");

    const uint32_t aoff = ((wm + (lane & 15)) * 40 + ((lane >> 4) << 3)) * 2;
    const uint32_t boff = ((wn + (lane & 7) + ((lane >> 4) << 3)) * 40 + (lane & 8)) * 2;

    for (int kt = 0; kt < KT; ++kt) {
        asm volatile("cp.async.wait_group 2;" ::: "memory");
        __syncthreads();
        const uint32_t sb = sbase + (kt & 3) * STAGEB;

        #pragma unroll
        for (int ks = 0; ks < 2; ++ks) {
            const uint32_t kc2 = ks * 32;
            uint32_t ahf[4][4], alf[4][4], bhf[4][2], blf[4][2];
            #pragma unroll
            for (int mt = 0; mt < 4; mt++) {
                ldsm4(ahf[mt], sb + aoff + kc2 + mt * 1280);
                ldsm4(alf[mt], sb + 10240 + aoff + kc2 + mt * 1280);
            }
            #pragma unroll
            for (int n2 = 0; n2 < 2; n2++) {
                uint32_t r[4];
                ldsm4(r, sb + 20480 + boff + kc2 + n2 * 1280);
                bhf[n2 * 2][0] = r[0]; bhf[n2 * 2][1] = r[1];
                bhf[n2 * 2 + 1][0] = r[2]; bhf[n2 * 2 + 1][1] = r[3];
                ldsm4(r, sb + 30720 + boff + kc2 + n2 * 1280);
                blf[n2 * 2][0] = r[0]; blf[n2 * 2][1] = r[1];
                blf[n2 * 2 + 1][0] = r[2]; blf[n2 * 2 + 1][1] = r[3];
            }
            #pragma unroll
            for (int mt = 0; mt < 4; mt++)
                #pragma unroll
                for (int nt = 0; nt < 4; nt++) {
                    mma16816(acc[mt][nt], ahf[mt], bhf[nt]);   // hi*hi
                    mma16816(acc[mt][nt], ahf[mt], blf[nt]);   // hi*lo
                    mma16816(acc[mt][nt], alf[mt], bhf[nt]);   // lo*hi
                }
        }
        __syncthreads();
        if (kt + 3 < KT) LOAD_STAGE(kt + 3);
        asm volatile("cp.async.commit_group;" ::: "memory");
    }

    #pragma unroll
    for (int mt = 0; mt < 4; mt++) {
        const int row = bm + wm + mt * 16 + (lane >> 2);
        float* r0 = C + (size_t)row * ldc + bn + wn + (lane & 3) * 2;
        float* r1 = r0 + (size_t)8 * ldc;
        #pragma unroll
        for (int nt = 0; nt < 4; nt++) {
            *(float2*)(r0 + nt * 8) = make_float2(acc[mt][nt][0], acc[mt][nt][1]);
            *(float2*)(r1 + nt * 8) = make_float2(acc[mt][nt][2], acc[mt][nt][3]);
        }
    }
#undef LOAD_STAGE
}

// ---------------------------------------------------------------------------
// Single-fp16 NT GEMM (1 mma term) — used for GEMM2 (out = P @ W).
// Same structure as gemm_hsplit without the lo planes.
// Stage: A 10240 B | B 10240 B -> STAGEB1 = 20480, 4 stages = 81920.
// ---------------------------------------------------------------------------
#define STAGEB1 20480
#define GSMEM1  (4 * STAGEB1)   // 81920

__global__ __launch_bounds__(256, 1) void gemm_h16(
    const __half* __restrict__ A, const __half* __restrict__ B,
    float* __restrict__ C, int lda, int ldb, int ldc, int KT)
{
    extern __shared__ __align__(16) char smem[];
    const uint32_t sbase = smem_u32_of(smem);
    const int tid  = threadIdx.x;
    const int lane = tid & 31;
    const int wid  = tid >> 5;
    const int wm   = (wid >> 2) * 64;
    const int wn   = (wid & 3) * 32;
    const int bm   = blockIdx.y * 128;
    const int bn   = blockIdx.x * 128;

    const int lr = tid >> 2;
    const int lc = tid & 3;
    const __half* pA = A + (size_t)(bm + lr) * lda + lc * 8;
    const __half* pB = B + (size_t)(bn + lr) * ldb + lc * 8;
    const size_t rstepA = (size_t)64 * lda;
    const size_t rstepB = (size_t)64 * ldb;
    const uint32_t so = lr * 80 + lc * 16;

    float acc[4][4][4];
    #pragma unroll
    for (int i = 0; i < 4; i++)
        #pragma unroll
        for (int j = 0; j < 4; j++)
            #pragma unroll
            for (int k = 0; k < 4; k++) acc[i][j][k] = 0.f;

#define LOAD_STAGE1(kt)                                                       \
    do {                                                                      \
        const int _k0 = (kt) * 32;                                            \
        const uint32_t _sb = sbase + ((kt) & 3) * STAGEB1 + so;               \
        cp16(_sb + 0,     pA + _k0);                                          \
        cp16(_sb + 5120,  pA + _k0 + rstepA);                                 \
        cp16(_sb + 10240, pB + _k0);                                          \
        cp16(_sb + 15360, pB + _k0 + rstepB);                                 \
    } while (0)

    LOAD_STAGE1(0); asm volatile("cp.async.commit_group;" ::: "memory");
    LOAD_STAGE1(1); asm volatile("cp.async.commit_group;" ::: "memory");
    LOAD_STAGE1(2); asm volatile("cp.async.commit_group;" ::: "memory");

    const uint32_t aoff = ((wm + (lane & 15)) * 40 + ((lane >> 4) << 3)) * 2;
    const uint32_t boff = ((wn + (lane & 7) + ((lane >> 4) << 3)) * 40 + (lane & 8)) * 2;

    for (int kt = 0; kt < KT; ++kt) {
        asm volatile("cp.async.wait_group 2;" ::: "memory");
        __syncthreads();
        const uint32_t sb = sbase + (kt & 3) * STAGEB1;

        #pragma unroll
        for (int ks = 0; ks < 2; ++ks) {
            const uint32_t kc2 = ks * 32;
            uint32_t af[4][4], bf[4][2];
            #pragma unroll
            for (int mt = 0; mt < 4; mt++)
                ldsm4(af[mt], sb + aoff + kc2 + mt * 1280);
            #pragma unroll
            for (int n2 = 0; n2 < 2; n2++) {
                uint32_t r[4];
                ldsm4(r, sb + 10240 + boff + kc2 + n2 * 1280);
                bf[n2 * 2][0] = r[0]; bf[n2 * 2][1] = r[1];
                bf[n2 * 2 + 1][0] = r[2]; bf[n2 * 2 + 1][1] = r[3];
            }
            #pragma unroll
            for (int mt = 0; mt < 4; mt++)
                #pragma unroll
                for (int nt = 0; nt < 4; nt++)
                    mma16816(acc[mt][nt], af[mt], bf[nt]);
        }
        __syncthreads();
        if (kt + 3 < KT) LOAD_STAGE1(kt + 3);
        asm volatile("cp.async.commit_group;" ::: "memory");
    }

    #pragma unroll
    for (int mt = 0; mt < 4; mt++) {
        const int row = bm + wm + mt * 16 + (lane >> 2);
        float* r0 = C + (size_t)row * ldc + bn + wn + (lane & 3) * 2;
        float* r1 = r0 + (size_t)8 * ldc;
        #pragma unroll
        for (int nt = 0; nt < 4; nt++) {
            *(float2*)(r0 + nt * 8) = make_float2(acc[mt][nt][0], acc[mt][nt][1]);
            *(float2*)(r1 + nt * 8) = make_float2(acc[mt][nt][2], acc[mt][nt][3]);
        }
    }
#undef LOAD_STAGE1
}

// ---------------------------------------------------------------------------
// Launch
// ---------------------------------------------------------------------------
extern "C" void kernel_launch(void* const* d_in, const int* in_sizes, int n_in,
                              void* d_out, int out_size)
{
    const float* x = (const float*)d_in[0];   // [16384, 1024]
    const float* w = (const float*)d_in[1];   // [4096, 1024]
    float* out = (float*)d_out;               // [16384, 1024]

    float *xscale, *wscale, *scores;
    __half *xhi, *xlo, *whi, *wlo, *wthi, *phi;
    cudaGetSymbolAddress((void**)&xscale, g_xscale);
    cudaGetSymbolAddress((void**)&wscale, g_wscale);
    cudaGetSymbolAddress((void**)&scores, g_scores);
    cudaGetSymbolAddress((void**)&xhi, g_xhi);
    cudaGetSymbolAddress((void**)&xlo, g_xlo);
    cudaGetSymbolAddress((void**)&whi, g_whi);
    cudaGetSymbolAddress((void**)&wlo, g_wlo);
    cudaGetSymbolAddress((void**)&wthi, g_wthi);
    cudaGetSymbolAddress((void**)&phi, g_phi);

    cudaFuncSetAttribute(gemm_hsplit, cudaFuncAttributeMaxDynamicSharedMemorySize,
                         GSMEM);
    cudaFuncSetAttribute(gemm_h16, cudaFuncAttributeMaxDynamicSharedMemorySize,
                         GSMEM1);

    // Prep: rms scales; scaled fp16 splits; W transpose (fp16)
    rms_scale_kernel<<<MROWS, 256>>>(x, xscale);
    rms_scale_kernel<<<DF,    256>>>(w, wscale);
    scale_split_kernel<<<(MROWS * (DM / 4)) / 256, 256>>>(x, xscale, xhi, xlo);
    scale_split_kernel<<<(DF * (DM / 4)) / 256, 256>>>(w, wscale, whi, wlo);
    {
        dim3 g(DM / 32, DF / 32), b(32, 32);
        wt_kernel<<<g, b>>>(w, wthi);
    }

    // GEMM1 (3-term exact): scores[m,n] = (xs*x)_m . (ws*w)_n
    {
        dim3 g(DF / 128, MROWS / 128);   // 32 x 128
        gemm_hsplit<<<g, 256, GSMEM>>>(xhi, xlo, whi, wlo, scores,
                                       DM, DM, DF, DM / 32);
    }

    // softmax rows -> fp16 probs
    softmax_h<<<MROWS, 256>>>(scores, phi);

    // GEMM2 (1-term fp16): out[m,d] = sum_c probs[m,c] * w[c,d]
    {
        dim3 g(DM / 128, MROWS / 128);   // 8 x 128
        gemm_h16<<<g, 256, GSMEM1>>>(phi, wthi, out, DF, DF, DM, DF / 32);
    }
}